// round 9
// baseline (speedup 1.0000x reference)
#include <cuda_runtime.h>
#include <cuda_fp16.h>
#include <math.h>
#include <stdint.h>

#define HEADS   16
#define DK      64
#define DMODEL  1024
#define NQ      1024
#define BATCH   8
#define MSLOT   8
#define NKV     1032
#define NKV_PAD 1088
#define ROWS    (NQ * BATCH)

// ------------------------- device scratch (no allocs allowed) ---------------
__device__ __half g_inh[(size_t)3 * ROWS * DMODEL];   // fp16 of q/k/v inputs
__device__ __half g_wh[(size_t)3 * DMODEL * DMODEL];  // fp16(in_proj_weight)
__device__ __half g_woh[(size_t)DMODEL * DMODEL];     // fp16(out_w)
__device__ __half g_q[(size_t)BATCH * HEADS * NQ * DK];
__device__ __half g_k[(size_t)BATCH * HEADS * NKV_PAD * DK];
__device__ __half g_v[(size_t)BATCH * HEADS * NKV_PAD * DK];
__device__ __half g_aoh[(size_t)ROWS * DMODEL];       // attn out (row = n*B+b)

// ------------------------- helpers ------------------------------------------
__device__ __forceinline__ uint32_t s2u(const void* p) {
    uint32_t a;
    asm("{ .reg .u64 t; cvta.to.shared.u64 t, %1; cvt.u32.u64 %0, t; }"
        : "=r"(a) : "l"(p));
    return a;
}

__device__ __forceinline__ void cpasync16(uint32_t dst, const void* src) {
    asm volatile("cp.async.cg.shared.global [%0], [%1], 16;"
                 :: "r"(dst), "l"(src));
}

#define LDM_X4(r, addr) \
    asm volatile("ldmatrix.sync.aligned.m8n8.x4.shared.b16 {%0,%1,%2,%3}, [%4];" \
                 : "=r"((r)[0]), "=r"((r)[1]), "=r"((r)[2]), "=r"((r)[3]) \
                 : "r"(addr))

#define LDM_X4_T(r, addr) \
    asm volatile("ldmatrix.sync.aligned.m8n8.x4.trans.shared.b16 {%0,%1,%2,%3}, [%4];" \
                 : "=r"((r)[0]), "=r"((r)[1]), "=r"((r)[2]), "=r"((r)[3]) \
                 : "r"(addr))

__device__ __forceinline__ void mma16816(float* c, const uint32_t* a,
                                         uint32_t b0, uint32_t b1) {
    asm volatile(
        "mma.sync.aligned.m16n8k16.row.col.f32.f16.f16.f32 "
        "{%0,%1,%2,%3}, {%4,%5,%6,%7}, {%8,%9}, {%0,%1,%2,%3};"
        : "+f"(c[0]), "+f"(c[1]), "+f"(c[2]), "+f"(c[3])
        : "r"(a[0]), "r"(a[1]), "r"(a[2]), "r"(a[3]), "r"(b0), "r"(b1));
}

__device__ __forceinline__ uint32_t packh2(float x, float y) {
    __half2 h = __floats2half2_rn(x, y);
    return *(uint32_t*)&h;
}

// ------------------------- conversion prepass (hi only) ---------------------
__global__ void convert_kernel(const float* __restrict__ q, const float* __restrict__ k,
                               const float* __restrict__ v, const float* __restrict__ wi,
                               const float* __restrict__ wo) {
    size_t i = (size_t)blockIdx.x * blockDim.x + threadIdx.x;
    const size_t NIN = 2097152;   // float4 per input tensor (8192*1024/4)
    if (i < 3 * NIN) {
        int which = (int)(i / NIN);
        size_t off = (i - (size_t)which * NIN) * 4;
        const float* s = (which == 0) ? q : (which == 1) ? k : v;
        float4 f = *(const float4*)(s + off);
        __half hv[4] = {__float2half_rn(f.x), __float2half_rn(f.y),
                        __float2half_rn(f.z), __float2half_rn(f.w)};
        *(uint2*)&g_inh[(size_t)which * 8388608 + off] = *(uint2*)hv;
    } else if (i < 3 * NIN + 786432) {
        size_t off = (i - 3 * NIN) * 4;
        float4 f = *(const float4*)(wi + off);
        __half hv[4] = {__float2half_rn(f.x), __float2half_rn(f.y),
                        __float2half_rn(f.z), __float2half_rn(f.w)};
        *(uint2*)&g_wh[off] = *(uint2*)hv;
    } else if (i < 3 * NIN + 786432 + 262144) {
        size_t off = (i - 3 * NIN - 786432) * 4;
        float4 f = *(const float4*)(wo + off);
        __half hv[4] = {__float2half_rn(f.x), __float2half_rn(f.y),
                        __float2half_rn(f.z), __float2half_rn(f.w)};
        *(uint2*)&g_woh[off] = *(uint2*)hv;
    }
}

// ------------------------- memory slot / pad fill ---------------------------
__global__ void fill_mem_kernel(const float* __restrict__ m_k,
                                const float* __restrict__ m_v) {
    int idx = blockIdx.x * blockDim.x + threadIdx.x;
    if (idx >= BATCH * HEADS * 64 * DK) return;
    int d = idx & 63;
    int s = (idx >> 6) & 63;
    int h = (idx >> 12) & 15;
    int b = idx >> 16;
    size_t o = (((size_t)(b * HEADS + h)) * NKV_PAD + 1024 + s) * DK + d;
    if (s < MSLOT) {
        g_k[o] = __float2half_rn(32.0f * m_k[s * DMODEL + h * 64 + d]);
        g_v[o] = __float2half_rn(2.8284271247461903f * m_v[s * DMODEL + h * 64 + d]);
    } else {
        g_k[o] = __float2half_rn(0.0f);
        g_v[o] = __float2half_rn(0.0f);
    }
}

// ------------------------- HMMA GEMM (BK=64, 2-stage double buffer) ---------
static constexpr int TILE_BYTES = 128 * 128;         // 16KB per operand tile
static constexpr int STAGE_B = 2 * TILE_BYTES;       // 32KB
static constexpr int GEMM_SMEM = 2 * STAGE_B;        // 65536

template <int NT, int EPI>
__global__ void __launch_bounds__(256, 2) gemm_mma(const float* __restrict__ bias,
                                                   float* __restrict__ outp) {
    extern __shared__ __align__(128) char sm[];
    const uint32_t smb = s2u(sm);
    const int tid = threadIdx.x, warp = tid >> 5, lane = tid & 31;

    const int lin = blockIdx.y * gridDim.x + blockIdx.x;
    const int bandsz = gridDim.x * 8;
    const int band = lin / bandsz, rem = lin % bandsz;
    const int by = band * 8 + (rem & 7);
    const int bx = rem >> 3;
    const int rowbase = by * 128, colbase = bx * 128;
    const int wr = (warp >> 2) * 64, wc = (warp & 3) * 32;

    const __half *ah, *bhp;
    if (EPI == 0) {
        const int z = colbase >> 10;
        ah = g_inh + (size_t)z * 8388608;
        bhp = g_wh;
    } else {
        ah = g_aoh;
        bhp = g_woh;
    }

    float acc[4][4][4];
#pragma unroll
    for (int i = 0; i < 4; i++)
#pragma unroll
        for (int j = 0; j < 4; j++)
#pragma unroll
            for (int u = 0; u < 4; u++) acc[i][j][u] = 0.0f;

    auto issue = [&](int kt) {
        const int slot = kt & 1;
        const int k0 = kt << 6;
        const __half* Ag = ah + (size_t)rowbase * 1024 + k0;
        const __half* Bg = bhp + (size_t)colbase * 1024 + k0;
        const uint32_t dstS = smb + slot * STAGE_B;
#pragma unroll
        for (int c8 = 0; c8 < 8; c8++) {
            int idx = tid + c8 * 256;
            int isB = idx >> 10;
            int e = idx & 1023;
            int r = e >> 3, c = e & 7;
            const __half* src = (isB ? Bg : Ag) + (size_t)r * 1024 + c * 8;
            uint32_t dst = dstS + isB * TILE_BYTES + r * 128 + ((c ^ (r & 7)) * 16);
            cpasync16(dst, src);
        }
    };

    issue(0);
    asm volatile("cp.async.commit_group;" ::: "memory");

    for (int kt = 0; kt < NT; kt++) {
        if (kt + 1 < NT) issue(kt + 1);
        asm volatile("cp.async.commit_group;" ::: "memory");
        asm volatile("cp.async.wait_group 1;" ::: "memory");
        __syncthreads();

        const uint32_t aBase = smb + (kt & 1) * STAGE_B;
        const uint32_t bBase = aBase + TILE_BYTES;
#pragma unroll
        for (int k16 = 0; k16 < 4; k16++) {
            uint32_t a[4][4];
#pragma unroll
            for (int mt = 0; mt < 4; mt++) {
                int r = wr + mt * 16 + (lane & 15);
                int cc = k16 * 2 + (lane >> 4);
                LDM_X4(a[mt], aBase + r * 128 + ((cc ^ (r & 7)) * 16));
            }
            uint32_t b[2][4];
#pragma unroll
            for (int bt = 0; bt < 2; bt++) {
                int r = wc + bt * 16 + (lane & 7) + ((lane >> 4) & 1) * 8;
                int cc = k16 * 2 + ((lane >> 3) & 1);
                LDM_X4(b[bt], bBase + r * 128 + ((cc ^ (r & 7)) * 16));
            }
#pragma unroll
            for (int mt = 0; mt < 4; mt++)
#pragma unroll
                for (int nt = 0; nt < 4; nt++)
                    mma16816(acc[mt][nt], a[mt], b[nt >> 1][(nt & 1) * 2],
                             b[nt >> 1][(nt & 1) * 2 + 1]);
        }
        __syncthreads();
    }

    const int r0 = lane >> 2, cp = (lane & 3) * 2;
#pragma unroll
    for (int mt = 0; mt < 4; mt++) {
#pragma unroll
        for (int nt = 0; nt < 4; nt++) {
            const float* cc = acc[mt][nt];
            int gr = rowbase + wr + mt * 16 + r0;
            int gc = colbase + wc + nt * 8 + cp;
            if (EPI == 0) {
                const int z = gc >> 10;
                __half* dst = (z == 0) ? g_q : (z == 1) ? g_k : g_v;
                const int L = (z == 0) ? NQ : NKV_PAD;
                float b0 = __half2float(__float2half_rn(bias[gc]));
                float b1 = __half2float(__float2half_rn(bias[gc + 1]));
                int cz = gc & 1023;
                int hh = cz >> 6, dk = cz & 63;
#pragma unroll
                for (int rh = 0; rh < 2; rh++) {
                    int g = gr + rh * 8;
                    int n = g >> 3, bb = g & 7;
                    size_t o = (((size_t)(bb * HEADS + hh)) * L + n) * 64 + dk;
                    __half hv[2] = {__float2half_rn(cc[rh * 2] + b0),
                                    __float2half_rn(cc[rh * 2 + 1] + b1)};
                    *(uint32_t*)&dst[o] = *(uint32_t*)hv;
                }
            } else {
                float b0 = bias[gc], b1 = bias[gc + 1];
#pragma unroll
                for (int rh = 0; rh < 2; rh++) {
                    int g = gr + rh * 8;
                    float2 v = make_float2(cc[rh * 2] + b0, cc[rh * 2 + 1] + b1);
                    *(float2*)&outp[(size_t)g * 1024 + gc] = v;
                }
            }
        }
    }
}

// ------------------------- flash attention (32 q-rows per warp) -------------
// Block: 256 q rows, 8 warps x 32 rows (2 m-tiles of 16). KV tiles of 64,
// 3-stage cp.async ring, one __syncthreads per tile. 1 CTA/SM (regs-bound).
static constexpr int ATTN_SMEM = 32768 + 3 * 16384;   // Q 32KB + 3 KV stages

__global__ void __launch_bounds__(256, 1) attn_kernel(const float* __restrict__ mask) {
    extern __shared__ __align__(128) char smc[];
    const uint32_t smb = s2u(smc);
    const int tid = threadIdx.x, warp = tid >> 5, lane = tid & 31;
    const int qt = blockIdx.x, bh = blockIdx.y;
    const int q0 = qt * 256;
    const __half* qg = g_q + ((size_t)bh * NQ + q0) * DK;
    const __half* kg = g_k + (size_t)bh * NKV_PAD * DK;
    const __half* vg = g_v + (size_t)bh * NKV_PAD * DK;

    auto issueKV = [&](int t) {
        const uint32_t base = smb + 32768 + (t % 3) * 16384;
        const __half* kp = kg + (size_t)t * 64 * 64;
        const __half* vp = vg + (size_t)t * 64 * 64;
#pragma unroll
        for (int it = 0; it < 2; it++) {
            int idx = tid + it * 256;
            int r = idx >> 3, c = idx & 7;
            uint32_t so = r * 128 + ((c ^ (r & 7)) * 16);
            cpasync16(base + so, kp + (size_t)r * 64 + c * 8);
            cpasync16(base + 8192 + so, vp + (size_t)r * 64 + c * 8);
        }
    };

    issueKV(0);
    asm volatile("cp.async.commit_group;" ::: "memory");
    issueKV(1);
    asm volatile("cp.async.commit_group;" ::: "memory");

    // ---- stage Q (256 x 64 fp16, swizzled) ----
#pragma unroll
    for (int it = 0; it < 8; it++) {
        int idx = tid + it * 256;           // 2048 chunks
        int r = idx >> 3, c = idx & 7;
        *(uint4*)(smc + r * 128 + ((c ^ (r & 7)) * 16)) =
            *(const uint4*)(qg + (size_t)r * 64 + c * 8);
    }
    __syncthreads();

    // per-warp Q fragments for 2 m-tiles, scaled by 1/8
    uint32_t qa[2][4][4];
    {
        const __half2 sc8 = __floats2half2_rn(0.125f, 0.125f);
#pragma unroll
        for (int mt = 0; mt < 2; mt++) {
            int r = warp * 32 + mt * 16 + (lane & 7) + ((lane >> 3) & 1) * 8;
#pragma unroll
            for (int u = 0; u < 4; u++) {
                int c = u * 2 + (lane >> 4);
                LDM_X4(qa[mt][u], smb + r * 128 + ((c ^ (r & 7)) * 16));
#pragma unroll
                for (int j = 0; j < 4; j++) {
                    __half2 h = __hmul2(*(__half2*)&qa[mt][u][j], sc8);
                    qa[mt][u][j] = *(uint32_t*)&h;
                }
            }
        }
    }

    float o[2][8][4];
#pragma unroll
    for (int mt = 0; mt < 2; mt++)
#pragma unroll
        for (int n = 0; n < 8; n++)
#pragma unroll
            for (int j = 0; j < 4; j++) o[mt][n][j] = 0.0f;
    float mprevA[2] = {-1e30f, -1e30f}, mprevB[2] = {-1e30f, -1e30f};
    float laccA[2] = {0.0f, 0.0f}, laccB[2] = {0.0f, 0.0f};

    const int rA = lane >> 2;
    const float* mrow = mask + ((size_t)bh * NQ + q0 + warp * 32 + rA) * NQ +
                        2 * (lane & 3);

    for (int t = 0; t < 17; t++) {
        asm volatile("cp.async.wait_group 1;" ::: "memory");
        __syncthreads();

        const uint32_t kb = smb + 32768 + (t % 3) * 16384;
        const uint32_t vb = kb + 8192;

        // ---- init S with the additive mask ----
        float s[2][8][4];
        if (t < 16) {
#pragma unroll
            for (int mt = 0; mt < 2; mt++) {
                const float* mA = mrow + (size_t)(mt * 16) * NQ + t * 64;
                const float* mB = mA + (size_t)8 * NQ;
#pragma unroll
                for (int n = 0; n < 8; n++) {
                    float2 xa = *(const float2*)(mA + n * 8);
                    float2 xb = *(const float2*)(mB + n * 8);
                    s[mt][n][0] = xa.x; s[mt][n][1] = xa.y;
                    s[mt][n][2] = xb.x; s[mt][n][3] = xb.y;
                }
            }
        } else {
            // keys 1024-1031 (n==0) are memory slots (mask 0); rest padding
#pragma unroll
            for (int mt = 0; mt < 2; mt++) {
                s[mt][0][0] = s[mt][0][1] = s[mt][0][2] = s[mt][0][3] = 0.0f;
#pragma unroll
                for (int n = 1; n < 8; n++)
                    s[mt][n][0] = s[mt][n][1] = s[mt][n][2] = s[mt][n][3] = -1e30f;
            }
        }

        // ---- S += (Q/8) @ K^T : each K ldmatrix feeds 4 mma (2 m-tiles) ----
        {
            const int rn = (lane & 7) + ((lane >> 4) & 1) * 8;
            const int ck = (lane >> 3) & 1;
#pragma unroll
            for (int g = 0; g < 4; g++) {
                int r = g * 16 + rn;
#pragma unroll
                for (int u = 0; u < 4; u++) {
                    int c = u * 2 + ck;
                    uint32_t kb4[4];
                    LDM_X4(kb4, kb + r * 128 + ((c ^ (r & 7)) * 16));
#pragma unroll
                    for (int mt = 0; mt < 2; mt++) {
                        mma16816(s[mt][2 * g],     qa[mt][u], kb4[0], kb4[1]);
                        mma16816(s[mt][2 * g + 1], qa[mt][u], kb4[2], kb4[3]);
                    }
                }
            }
        }

        // ---- online softmax per m-tile ----
        uint32_t pf[2][4][4];
#pragma unroll
        for (int mt = 0; mt < 2; mt++) {
            float mxA = -1e30f, mxB = -1e30f;
#pragma unroll
            for (int n = 0; n < 8; n++) {
                mxA = fmaxf(mxA, fmaxf(s[mt][n][0], s[mt][n][1]));
                mxB = fmaxf(mxB, fmaxf(s[mt][n][2], s[mt][n][3]));
            }
            mxA = fmaxf(mxA, __shfl_xor_sync(0xffffffffu, mxA, 1));
            mxA = fmaxf(mxA, __shfl_xor_sync(0xffffffffu, mxA, 2));
            mxB = fmaxf(mxB, __shfl_xor_sync(0xffffffffu, mxB, 1));
            mxB = fmaxf(mxB, __shfl_xor_sync(0xffffffffu, mxB, 2));
            float mnA = fmaxf(mprevA[mt], mxA), mnB = fmaxf(mprevB[mt], mxB);
            float aA = __expf(mprevA[mt] - mnA), aB = __expf(mprevB[mt] - mnB);
            mprevA[mt] = mnA; mprevB[mt] = mnB;

            float sumA = 0.0f, sumB = 0.0f;
#pragma unroll
            for (int n = 0; n < 8; n++) {
                float p0 = __expf(s[mt][n][0] - mnA);
                float p1 = __expf(s[mt][n][1] - mnA);
                float p2 = __expf(s[mt][n][2] - mnB);
                float p3 = __expf(s[mt][n][3] - mnB);
                sumA += p0 + p1; sumB += p2 + p3;
                pf[mt][n >> 1][(n & 1) * 2]     = packh2(p0, p1);
                pf[mt][n >> 1][(n & 1) * 2 + 1] = packh2(p2, p3);
            }
            sumA += __shfl_xor_sync(0xffffffffu, sumA, 1);
            sumA += __shfl_xor_sync(0xffffffffu, sumA, 2);
            sumB += __shfl_xor_sync(0xffffffffu, sumB, 1);
            sumB += __shfl_xor_sync(0xffffffffu, sumB, 2);
            laccA[mt] = laccA[mt] * aA + sumA;
            laccB[mt] = laccB[mt] * aB + sumB;
#pragma unroll
            for (int n = 0; n < 8; n++) {
                o[mt][n][0] *= aA; o[mt][n][1] *= aA;
                o[mt][n][2] *= aB; o[mt][n][3] *= aB;
            }
        }

        // ---- O += P @ V : each V ldmatrix feeds 4 mma (2 m-tiles) ----
        {
            int rr = (lane & 7) + ((lane >> 3) & 1) * 8;
#pragma unroll
            for (int u = 0; u < 4; u++) {
                int r = u * 16 + rr;
#pragma unroll
                for (int dp = 0; dp < 4; dp++) {
                    int c = dp * 2 + (lane >> 4);
                    uint32_t vb4[4];
                    LDM_X4_T(vb4, vb + r * 128 + ((c ^ (r & 7)) * 16));
#pragma unroll
                    for (int mt = 0; mt < 2; mt++) {
                        mma16816(o[mt][2 * dp],     pf[mt][u], vb4[0], vb4[1]);
                        mma16816(o[mt][2 * dp + 1], pf[mt][u], vb4[2], vb4[3]);
                    }
                }
            }
        }

        if (t + 2 < 17) issueKV(t + 2);
        asm volatile("cp.async.commit_group;" ::: "memory");
    }

    // ---- finalize: O /= l, write fp16 to g_aoh (row = q*B + b) ----
    const int b = bh >> 4, h = bh & 15;
#pragma unroll
    for (int mt = 0; mt < 2; mt++) {
        const int qrA = q0 + warp * 32 + mt * 16 + rA;
        const float invA = 1.0f / laccA[mt], invB = 1.0f / laccB[mt];
#pragma unroll
        for (int n = 0; n < 8; n++) {
            int dk = h * 64 + n * 8 + 2 * (lane & 3);
            {
                __half hv[2] = {__float2half_rn(o[mt][n][0] * invA),
                                __float2half_rn(o[mt][n][1] * invA)};
                *(uint32_t*)&g_aoh[((size_t)qrA * BATCH + b) * DMODEL + dk] =
                    *(uint32_t*)hv;
            }
            {
                __half hv[2] = {__float2half_rn(o[mt][n][2] * invB),
                                __float2half_rn(o[mt][n][3] * invB)};
                *(uint32_t*)&g_aoh[((size_t)(qrA + 8) * BATCH + b) * DMODEL + dk] =
                    *(uint32_t*)hv;
            }
        }
    }
}

// ------------------------- launch -------------------------------------------
extern "C" void kernel_launch(void* const* d_in, const int* in_sizes, int n_in,
                              void* d_out, int out_size) {
    const float* queries = (const float*)d_in[0];
    const float* keys    = (const float*)d_in[1];
    const float* values  = (const float*)d_in[2];
    const float* m_k     = (const float*)d_in[3];
    const float* m_v     = (const float*)d_in[4];
    const float* mask    = (const float*)d_in[5];
    const float* in_w    = (const float*)d_in[6];
    const float* in_b    = (const float*)d_in[7];
    const float* out_w   = (const float*)d_in[8];
    const float* out_b   = (const float*)d_in[9];
    float* out = (float*)d_out;
    (void)in_sizes; (void)n_in; (void)out_size;

    cudaFuncSetAttribute(attn_kernel, cudaFuncAttributeMaxDynamicSharedMemorySize,
                         ATTN_SMEM);
    cudaFuncSetAttribute(gemm_mma<16, 0>, cudaFuncAttributeMaxDynamicSharedMemorySize,
                         GEMM_SMEM);
    cudaFuncSetAttribute(gemm_mma<16, 1>, cudaFuncAttributeMaxDynamicSharedMemorySize,
                         GEMM_SMEM);

    convert_kernel<<<28672, 256>>>(queries, keys, values, in_w, out_w);
    fill_mem_kernel<<<2048, 256>>>(m_k, m_v);
    gemm_mma<16, 0><<<dim3(24, 64), 256, GEMM_SMEM>>>(in_b, nullptr);  // QKV proj
    attn_kernel<<<dim3(4, 128), 256, ATTN_SMEM>>>(mask);
    gemm_mma<16, 1><<<dim3(8, 64), 256, GEMM_SMEM>>>(out_b, out);      // out proj
}

// round 10
// speedup vs baseline: 1.0861x; 1.0861x over previous
#include <cuda_runtime.h>
#include <cuda_fp16.h>
#include <math.h>
#include <stdint.h>

#define HEADS   16
#define DK      64
#define DMODEL  1024
#define NQ      1024
#define BATCH   8
#define MSLOT   8
#define NKV     1032
#define NKV_PAD 1088
#define ROWS    (NQ * BATCH)

// ------------------------- device scratch (no allocs allowed) ---------------
__device__ __half g_inh[(size_t)3 * ROWS * DMODEL];   // fp16 of q/k/v inputs
__device__ __half g_wh[(size_t)3 * DMODEL * DMODEL];  // fp16(in_proj_weight)
__device__ __half g_woh[(size_t)DMODEL * DMODEL];     // fp16(out_w)
__device__ __half g_q[(size_t)BATCH * HEADS * NQ * DK];
__device__ __half g_k[(size_t)BATCH * HEADS * NKV_PAD * DK];
__device__ __half g_v[(size_t)BATCH * HEADS * NKV_PAD * DK];
__device__ __half g_aoh[(size_t)ROWS * DMODEL];       // attn out (row = n*B+b)

// ------------------------- helpers ------------------------------------------
__device__ __forceinline__ uint32_t s2u(const void* p) {
    uint32_t a;
    asm("{ .reg .u64 t; cvta.to.shared.u64 t, %1; cvt.u32.u64 %0, t; }"
        : "=r"(a) : "l"(p));
    return a;
}

__device__ __forceinline__ void cpasync16(uint32_t dst, const void* src) {
    asm volatile("cp.async.cg.shared.global [%0], [%1], 16;"
                 :: "r"(dst), "l"(src));
}

#define LDM_X4(r, addr) \
    asm volatile("ldmatrix.sync.aligned.m8n8.x4.shared.b16 {%0,%1,%2,%3}, [%4];" \
                 : "=r"((r)[0]), "=r"((r)[1]), "=r"((r)[2]), "=r"((r)[3]) \
                 : "r"(addr))

#define LDM_X4_T(r, addr) \
    asm volatile("ldmatrix.sync.aligned.m8n8.x4.trans.shared.b16 {%0,%1,%2,%3}, [%4];" \
                 : "=r"((r)[0]), "=r"((r)[1]), "=r"((r)[2]), "=r"((r)[3]) \
                 : "r"(addr))

__device__ __forceinline__ void mma16816(float* c, const uint32_t* a,
                                         uint32_t b0, uint32_t b1) {
    asm volatile(
        "mma.sync.aligned.m16n8k16.row.col.f32.f16.f16.f32 "
        "{%0,%1,%2,%3}, {%4,%5,%6,%7}, {%8,%9}, {%0,%1,%2,%3};"
        : "+f"(c[0]), "+f"(c[1]), "+f"(c[2]), "+f"(c[3])
        : "r"(a[0]), "r"(a[1]), "r"(a[2]), "r"(a[3]), "r"(b0), "r"(b1));
}

__device__ __forceinline__ uint32_t packh2(float x, float y) {
    __half2 h = __floats2half2_rn(x, y);
    return *(uint32_t*)&h;
}

// ------------------------- conversion prepass (hi only) ---------------------
__global__ void convert_kernel(const float* __restrict__ q, const float* __restrict__ k,
                               const float* __restrict__ v, const float* __restrict__ wi,
                               const float* __restrict__ wo) {
    size_t i = (size_t)blockIdx.x * blockDim.x + threadIdx.x;
    const size_t NIN = 2097152;   // float4 per input tensor (8192*1024/4)
    if (i < 3 * NIN) {
        int which = (int)(i / NIN);
        size_t off = (i - (size_t)which * NIN) * 4;
        const float* s = (which == 0) ? q : (which == 1) ? k : v;
        float4 f = *(const float4*)(s + off);
        __half hv[4] = {__float2half_rn(f.x), __float2half_rn(f.y),
                        __float2half_rn(f.z), __float2half_rn(f.w)};
        *(uint2*)&g_inh[(size_t)which * 8388608 + off] = *(uint2*)hv;
    } else if (i < 3 * NIN + 786432) {
        size_t off = (i - 3 * NIN) * 4;
        float4 f = *(const float4*)(wi + off);
        __half hv[4] = {__float2half_rn(f.x), __float2half_rn(f.y),
                        __float2half_rn(f.z), __float2half_rn(f.w)};
        *(uint2*)&g_wh[off] = *(uint2*)hv;
    } else if (i < 3 * NIN + 786432 + 262144) {
        size_t off = (i - 3 * NIN - 786432) * 4;
        float4 f = *(const float4*)(wo + off);
        __half hv[4] = {__float2half_rn(f.x), __float2half_rn(f.y),
                        __float2half_rn(f.z), __float2half_rn(f.w)};
        *(uint2*)&g_woh[off] = *(uint2*)hv;
    }
}

// ------------------------- memory slot / pad fill ---------------------------
__global__ void fill_mem_kernel(const float* __restrict__ m_k,
                                const float* __restrict__ m_v) {
    int idx = blockIdx.x * blockDim.x + threadIdx.x;
    if (idx >= BATCH * HEADS * 64 * DK) return;
    int d = idx & 63;
    int s = (idx >> 6) & 63;
    int h = (idx >> 12) & 15;
    int b = idx >> 16;
    size_t o = (((size_t)(b * HEADS + h)) * NKV_PAD + 1024 + s) * DK + d;
    if (s < MSLOT) {
        g_k[o] = __float2half_rn(32.0f * m_k[s * DMODEL + h * 64 + d]);
        g_v[o] = __float2half_rn(2.8284271247461903f * m_v[s * DMODEL + h * 64 + d]);
    } else {
        g_k[o] = __float2half_rn(0.0f);
        g_v[o] = __float2half_rn(0.0f);
    }
}

// ------------------------- HMMA GEMM (256x128 tile, BK=64, 2-stage) ---------
// 512 threads, 16 warps in 4x4 grid; warp tile 64x32 (identical inner loop
// to the R8 kernel, so per-output accumulation order is unchanged).
static constexpr int A_TILE = 256 * 128;             // 32KB (256 rows x 128B)
static constexpr int B_TILE = 128 * 128;             // 16KB
static constexpr int STAGE_B = A_TILE + B_TILE;      // 48KB
static constexpr int GEMM_SMEM = 2 * STAGE_B;        // 98304

template <int NT, int EPI>
__global__ void __launch_bounds__(512, 1) gemm_mma(const float* __restrict__ bias,
                                                   float* __restrict__ outp) {
    extern __shared__ __align__(128) char sm[];
    const uint32_t smb = s2u(sm);
    const int tid = threadIdx.x, warp = tid >> 5, lane = tid & 31;

    const int lin = blockIdx.y * gridDim.x + blockIdx.x;
    const int bandsz = gridDim.x * 8;
    const int band = lin / bandsz, rem = lin % bandsz;
    const int by = band * 8 + (rem & 7);
    const int bx = rem >> 3;
    const int rowbase = by * 256, colbase = bx * 128;
    const int wr = (warp >> 2) * 64, wc = (warp & 3) * 32;

    const __half *ah, *bhp;
    if (EPI == 0) {
        const int z = colbase >> 10;
        ah = g_inh + (size_t)z * 8388608;
        bhp = g_wh;
    } else {
        ah = g_aoh;
        bhp = g_woh;
    }

    float acc[4][4][4];
#pragma unroll
    for (int i = 0; i < 4; i++)
#pragma unroll
        for (int j = 0; j < 4; j++)
#pragma unroll
            for (int u = 0; u < 4; u++) acc[i][j][u] = 0.0f;

    auto issue = [&](int kt) {
        const int slot = kt & 1;
        const int k0 = kt << 6;
        const __half* Ag = ah + (size_t)rowbase * 1024 + k0;
        const __half* Bg = bhp + (size_t)colbase * 1024 + k0;
        const uint32_t dstS = smb + slot * STAGE_B;
#pragma unroll
        for (int c6 = 0; c6 < 6; c6++) {
            int idx = tid + c6 * 512;            // 3072 x 16B chunks
            if (idx < 2048) {                    // A: 256 rows x 8 chunks
                int r = idx >> 3, c = idx & 7;
                cpasync16(dstS + r * 128 + ((c ^ (r & 7)) * 16),
                          Ag + (size_t)r * 1024 + c * 8);
            } else {                             // B: 128 rows x 8 chunks
                int e = idx - 2048;
                int r = e >> 3, c = e & 7;
                cpasync16(dstS + A_TILE + r * 128 + ((c ^ (r & 7)) * 16),
                          Bg + (size_t)r * 1024 + c * 8);
            }
        }
    };

    issue(0);
    asm volatile("cp.async.commit_group;" ::: "memory");

    for (int kt = 0; kt < NT; kt++) {
        if (kt + 1 < NT) issue(kt + 1);
        asm volatile("cp.async.commit_group;" ::: "memory");
        asm volatile("cp.async.wait_group 1;" ::: "memory");
        __syncthreads();

        const uint32_t aBase = smb + (kt & 1) * STAGE_B;
        const uint32_t bBase = aBase + A_TILE;
#pragma unroll
        for (int k16 = 0; k16 < 4; k16++) {
            uint32_t a[4][4];
#pragma unroll
            for (int mt = 0; mt < 4; mt++) {
                int r = wr + mt * 16 + (lane & 15);
                int cc = k16 * 2 + (lane >> 4);
                LDM_X4(a[mt], aBase + r * 128 + ((cc ^ (r & 7)) * 16));
            }
            uint32_t b[2][4];
#pragma unroll
            for (int bt = 0; bt < 2; bt++) {
                int r = wc + bt * 16 + (lane & 7) + ((lane >> 4) & 1) * 8;
                int cc = k16 * 2 + ((lane >> 3) & 1);
                LDM_X4(b[bt], bBase + r * 128 + ((cc ^ (r & 7)) * 16));
            }
#pragma unroll
            for (int mt = 0; mt < 4; mt++)
#pragma unroll
                for (int nt = 0; nt < 4; nt++)
                    mma16816(acc[mt][nt], a[mt], b[nt >> 1][(nt & 1) * 2],
                             b[nt >> 1][(nt & 1) * 2 + 1]);
        }
        __syncthreads();
    }

    const int r0 = lane >> 2, cp = (lane & 3) * 2;
#pragma unroll
    for (int mt = 0; mt < 4; mt++) {
#pragma unroll
        for (int nt = 0; nt < 4; nt++) {
            const float* cc = acc[mt][nt];
            int gr = rowbase + wr + mt * 16 + r0;
            int gc = colbase + wc + nt * 8 + cp;
            if (EPI == 0) {
                const int z = gc >> 10;
                __half* dst = (z == 0) ? g_q : (z == 1) ? g_k : g_v;
                const int L = (z == 0) ? NQ : NKV_PAD;
                float b0 = __half2float(__float2half_rn(bias[gc]));
                float b1 = __half2float(__float2half_rn(bias[gc + 1]));
                int cz = gc & 1023;
                int hh = cz >> 6, dk = cz & 63;
#pragma unroll
                for (int rh = 0; rh < 2; rh++) {
                    int g = gr + rh * 8;
                    int n = g >> 3, bb = g & 7;
                    size_t o = (((size_t)(bb * HEADS + hh)) * L + n) * 64 + dk;
                    __half hv[2] = {__float2half_rn(cc[rh * 2] + b0),
                                    __float2half_rn(cc[rh * 2 + 1] + b1)};
                    *(uint32_t*)&dst[o] = *(uint32_t*)hv;
                }
            } else {
                float b0 = bias[gc], b1 = bias[gc + 1];
#pragma unroll
                for (int rh = 0; rh < 2; rh++) {
                    int g = gr + rh * 8;
                    float2 v = make_float2(cc[rh * 2] + b0, cc[rh * 2 + 1] + b1);
                    *(float2*)&outp[(size_t)g * 1024 + gc] = v;
                }
            }
        }
    }
}

// ------------------------- flash attention (R8 config: 16 q-rows/warp) ------
static constexpr int ATTN_SMEM = 16384 + 3 * 16384;   // Q + 3 KV stages

__global__ void __launch_bounds__(256, 2) attn_kernel(const float* __restrict__ mask) {
    extern __shared__ __align__(128) char smc[];
    const uint32_t smb = s2u(smc);
    const int tid = threadIdx.x, warp = tid >> 5, lane = tid & 31;
    const int qt = blockIdx.x, bh = blockIdx.y;
    const int q0 = qt * 128;
    const __half* qg = g_q + ((size_t)bh * NQ + q0) * DK;
    const __half* kg = g_k + (size_t)bh * NKV_PAD * DK;
    const __half* vg = g_v + (size_t)bh * NKV_PAD * DK;

    auto issueKV = [&](int t) {
        const uint32_t base = smb + 16384 + (t % 3) * 16384;
        const __half* kp = kg + (size_t)t * 64 * 64;
        const __half* vp = vg + (size_t)t * 64 * 64;
#pragma unroll
        for (int it = 0; it < 2; it++) {
            int idx = tid + it * 256;
            int r = idx >> 3, c = idx & 7;
            uint32_t so = r * 128 + ((c ^ (r & 7)) * 16);
            cpasync16(base + so, kp + (size_t)r * 64 + c * 8);
            cpasync16(base + 8192 + so, vp + (size_t)r * 64 + c * 8);
        }
    };

    issueKV(0);
    asm volatile("cp.async.commit_group;" ::: "memory");
    issueKV(1);
    asm volatile("cp.async.commit_group;" ::: "memory");

#pragma unroll
    for (int it = 0; it < 4; it++) {
        int idx = tid + it * 256;
        int r = idx >> 3, c = idx & 7;
        *(uint4*)(smc + r * 128 + ((c ^ (r & 7)) * 16)) =
            *(const uint4*)(qg + (size_t)r * 64 + c * 8);
    }
    __syncthreads();

    uint32_t qa[4][4];
    {
        const __half2 sc8 = __floats2half2_rn(0.125f, 0.125f);
        int r = warp * 16 + (lane & 7) + ((lane >> 3) & 1) * 8;
#pragma unroll
        for (int u = 0; u < 4; u++) {
            int c = u * 2 + (lane >> 4);
            LDM_X4(qa[u], smb + r * 128 + ((c ^ (r & 7)) * 16));
#pragma unroll
            for (int j = 0; j < 4; j++) {
                __half2 h = __hmul2(*(__half2*)&qa[u][j], sc8);
                qa[u][j] = *(uint32_t*)&h;
            }
        }
    }

    float o[8][4];
#pragma unroll
    for (int n = 0; n < 8; n++)
#pragma unroll
        for (int j = 0; j < 4; j++) o[n][j] = 0.0f;
    float mprevA = -1e30f, mprevB = -1e30f, laccA = 0.0f, laccB = 0.0f;

    const int rA = lane >> 2;
    const float* mrowA = mask + ((size_t)bh * NQ + q0 + warp * 16 + rA) * NQ +
                         2 * (lane & 3);
    const float* mrowB = mrowA + 8 * NQ;

    for (int t = 0; t < 17; t++) {
        asm volatile("cp.async.wait_group 1;" ::: "memory");
        __syncthreads();

        const uint32_t kb = smb + 16384 + (t % 3) * 16384;
        const uint32_t vb = kb + 8192;

        float s[8][4];
        if (t < 16) {
            const float* mA = mrowA + t * 64;
            const float* mB = mrowB + t * 64;
#pragma unroll
            for (int n = 0; n < 8; n++) {
                float2 xa = *(const float2*)(mA + n * 8);
                float2 xb = *(const float2*)(mB + n * 8);
                s[n][0] = xa.x; s[n][1] = xa.y;
                s[n][2] = xb.x; s[n][3] = xb.y;
            }
        } else {
            s[0][0] = s[0][1] = s[0][2] = s[0][3] = 0.0f;
#pragma unroll
            for (int n = 1; n < 8; n++)
                s[n][0] = s[n][1] = s[n][2] = s[n][3] = -1e30f;
        }

        {
            const int rn = (lane & 7) + ((lane >> 4) & 1) * 8;
            const int ck = (lane >> 3) & 1;
#pragma unroll
            for (int g = 0; g < 4; g++) {
                int r = g * 16 + rn;
#pragma unroll
                for (int u = 0; u < 4; u++) {
                    int c = u * 2 + ck;
                    uint32_t kb4[4];
                    LDM_X4(kb4, kb + r * 128 + ((c ^ (r & 7)) * 16));
                    mma16816(s[2 * g],     qa[u], kb4[0], kb4[1]);
                    mma16816(s[2 * g + 1], qa[u], kb4[2], kb4[3]);
                }
            }
        }

        float mxA = -1e30f, mxB = -1e30f;
#pragma unroll
        for (int n = 0; n < 8; n++) {
            mxA = fmaxf(mxA, fmaxf(s[n][0], s[n][1]));
            mxB = fmaxf(mxB, fmaxf(s[n][2], s[n][3]));
        }
        mxA = fmaxf(mxA, __shfl_xor_sync(0xffffffffu, mxA, 1));
        mxA = fmaxf(mxA, __shfl_xor_sync(0xffffffffu, mxA, 2));
        mxB = fmaxf(mxB, __shfl_xor_sync(0xffffffffu, mxB, 1));
        mxB = fmaxf(mxB, __shfl_xor_sync(0xffffffffu, mxB, 2));
        float mnA = fmaxf(mprevA, mxA), mnB = fmaxf(mprevB, mxB);
        float aA = __expf(mprevA - mnA), aB = __expf(mprevB - mnB);
        mprevA = mnA; mprevB = mnB;

        uint32_t pf[4][4];
        float sumA = 0.0f, sumB = 0.0f;
#pragma unroll
        for (int n = 0; n < 8; n++) {
            float p0 = __expf(s[n][0] - mnA);
            float p1 = __expf(s[n][1] - mnA);
            float p2 = __expf(s[n][2] - mnB);
            float p3 = __expf(s[n][3] - mnB);
            sumA += p0 + p1; sumB += p2 + p3;
            pf[n >> 1][(n & 1) * 2]     = packh2(p0, p1);
            pf[n >> 1][(n & 1) * 2 + 1] = packh2(p2, p3);
        }
        sumA += __shfl_xor_sync(0xffffffffu, sumA, 1);
        sumA += __shfl_xor_sync(0xffffffffu, sumA, 2);
        sumB += __shfl_xor_sync(0xffffffffu, sumB, 1);
        sumB += __shfl_xor_sync(0xffffffffu, sumB, 2);
        laccA = laccA * aA + sumA;
        laccB = laccB * aB + sumB;
#pragma unroll
        for (int n = 0; n < 8; n++) {
            o[n][0] *= aA; o[n][1] *= aA;
            o[n][2] *= aB; o[n][3] *= aB;
        }

        {
            int rr = (lane & 7) + ((lane >> 3) & 1) * 8;
#pragma unroll
            for (int u = 0; u < 4; u++) {
                int r = u * 16 + rr;
#pragma unroll
                for (int dp = 0; dp < 4; dp++) {
                    int c = dp * 2 + (lane >> 4);
                    uint32_t vb4[4];
                    LDM_X4_T(vb4, vb + r * 128 + ((c ^ (r & 7)) * 16));
                    mma16816(o[2 * dp],     pf[u], vb4[0], vb4[1]);
                    mma16816(o[2 * dp + 1], pf[u], vb4[2], vb4[3]);
                }
            }
        }

        if (t + 2 < 17) issueKV(t + 2);
        asm volatile("cp.async.commit_group;" ::: "memory");
    }

    const int b = bh >> 4, h = bh & 15;
    const int qrA = q0 + warp * 16 + rA;
    const float invA = 1.0f / laccA, invB = 1.0f / laccB;
#pragma unroll
    for (int n = 0; n < 8; n++) {
        int dk = h * 64 + n * 8 + 2 * (lane & 3);
        {
            __half hv[2] = {__float2half_rn(o[n][0] * invA),
                            __float2half_rn(o[n][1] * invA)};
            *(uint32_t*)&g_aoh[((size_t)qrA * BATCH + b) * DMODEL + dk] =
                *(uint32_t*)hv;
        }
        {
            __half hv[2] = {__float2half_rn(o[n][2] * invB),
                            __float2half_rn(o[n][3] * invB)};
            *(uint32_t*)&g_aoh[((size_t)(qrA + 8) * BATCH + b) * DMODEL + dk] =
                *(uint32_t*)hv;
        }
    }
}

// ------------------------- launch -------------------------------------------
extern "C" void kernel_launch(void* const* d_in, const int* in_sizes, int n_in,
                              void* d_out, int out_size) {
    const float* queries = (const float*)d_in[0];
    const float* keys    = (const float*)d_in[1];
    const float* values  = (const float*)d_in[2];
    const float* m_k     = (const float*)d_in[3];
    const float* m_v     = (const float*)d_in[4];
    const float* mask    = (const float*)d_in[5];
    const float* in_w    = (const float*)d_in[6];
    const float* in_b    = (const float*)d_in[7];
    const float* out_w   = (const float*)d_in[8];
    const float* out_b   = (const float*)d_in[9];
    float* out = (float*)d_out;
    (void)in_sizes; (void)n_in; (void)out_size;

    cudaFuncSetAttribute(attn_kernel, cudaFuncAttributeMaxDynamicSharedMemorySize,
                         ATTN_SMEM);
    cudaFuncSetAttribute(gemm_mma<16, 0>, cudaFuncAttributeMaxDynamicSharedMemorySize,
                         GEMM_SMEM);
    cudaFuncSetAttribute(gemm_mma<16, 1>, cudaFuncAttributeMaxDynamicSharedMemorySize,
                         GEMM_SMEM);

    convert_kernel<<<28672, 256>>>(queries, keys, values, in_w, out_w);
    fill_mem_kernel<<<2048, 256>>>(m_k, m_v);
    gemm_mma<16, 0><<<dim3(24, 32), 512, GEMM_SMEM>>>(in_b, nullptr);  // QKV proj
    attn_kernel<<<dim3(8, 128), 256, ATTN_SMEM>>>(mask);
    gemm_mma<16, 1><<<dim3(8, 32), 512, GEMM_SMEM>>>(out_b, out);      // out proj
}

// round 11
// speedup vs baseline: 1.1860x; 1.0920x over previous
#include <cuda_runtime.h>
#include <cuda_fp16.h>
#include <math.h>
#include <stdint.h>

#define HEADS   16
#define DK      64
#define DMODEL  1024
#define NQ      1024
#define BATCH   8
#define MSLOT   8
#define NKV     1032
#define NKV_PAD 1088
#define ROWS    (NQ * BATCH)

// ------------------------- device scratch (no allocs allowed) ---------------
__device__ __half g_inh[(size_t)3 * ROWS * DMODEL];   // fp16 of q/k/v inputs
__device__ __half g_wh[(size_t)3 * DMODEL * DMODEL];  // fp16(in_proj_weight)
__device__ __half g_woh[(size_t)DMODEL * DMODEL];     // fp16(out_w)
__device__ __half g_q[(size_t)BATCH * HEADS * NQ * DK];
__device__ __half g_k[(size_t)BATCH * HEADS * NKV_PAD * DK];
__device__ __half g_v[(size_t)BATCH * HEADS * NKV_PAD * DK];
__device__ __half g_aoh[(size_t)ROWS * DMODEL];       // attn out (row = n*B+b)

// ------------------------- helpers ------------------------------------------
__device__ __forceinline__ uint32_t s2u(const void* p) {
    uint32_t a;
    asm("{ .reg .u64 t; cvta.to.shared.u64 t, %1; cvt.u32.u64 %0, t; }"
        : "=r"(a) : "l"(p));
    return a;
}

__device__ __forceinline__ void cpasync16(uint32_t dst, const void* src) {
    asm volatile("cp.async.cg.shared.global [%0], [%1], 16;"
                 :: "r"(dst), "l"(src));
}

#define LDM_X4(r, addr) \
    asm volatile("ldmatrix.sync.aligned.m8n8.x4.shared.b16 {%0,%1,%2,%3}, [%4];" \
                 : "=r"((r)[0]), "=r"((r)[1]), "=r"((r)[2]), "=r"((r)[3]) \
                 : "r"(addr))

#define LDM_X4_T(r, addr) \
    asm volatile("ldmatrix.sync.aligned.m8n8.x4.trans.shared.b16 {%0,%1,%2,%3}, [%4];" \
                 : "=r"((r)[0]), "=r"((r)[1]), "=r"((r)[2]), "=r"((r)[3]) \
                 : "r"(addr))

__device__ __forceinline__ void mma16816(float* c, const uint32_t* a,
                                         uint32_t b0, uint32_t b1) {
    asm volatile(
        "mma.sync.aligned.m16n8k16.row.col.f32.f16.f16.f32 "
        "{%0,%1,%2,%3}, {%4,%5,%6,%7}, {%8,%9}, {%0,%1,%2,%3};"
        : "+f"(c[0]), "+f"(c[1]), "+f"(c[2]), "+f"(c[3])
        : "r"(a[0]), "r"(a[1]), "r"(a[2]), "r"(a[3]), "r"(b0), "r"(b1));
}

__device__ __forceinline__ uint32_t packh2(float x, float y) {
    __half2 h = __floats2half2_rn(x, y);
    return *(uint32_t*)&h;
}

// ------------------------- conversion + memory-slot prepass -----------------
__global__ void convert_kernel(const float* __restrict__ q, const float* __restrict__ k,
                               const float* __restrict__ v, const float* __restrict__ wi,
                               const float* __restrict__ wo,
                               const float* __restrict__ m_k,
                               const float* __restrict__ m_v) {
    size_t i = (size_t)blockIdx.x * blockDim.x + threadIdx.x;
    const size_t NIN = 2097152;   // float4 per input tensor (8192*1024/4)
    const size_t W_END = 3 * NIN + 786432;
    const size_t WO_END = W_END + 262144;
    const size_t FILL_END = WO_END + 524288;
    if (i < 3 * NIN) {
        int which = (int)(i / NIN);
        size_t off = (i - (size_t)which * NIN) * 4;
        const float* s = (which == 0) ? q : (which == 1) ? k : v;
        float4 f = *(const float4*)(s + off);
        __half hv[4] = {__float2half_rn(f.x), __float2half_rn(f.y),
                        __float2half_rn(f.z), __float2half_rn(f.w)};
        *(uint2*)&g_inh[(size_t)which * 8388608 + off] = *(uint2*)hv;
    } else if (i < W_END) {
        size_t off = (i - 3 * NIN) * 4;
        float4 f = *(const float4*)(wi + off);
        __half hv[4] = {__float2half_rn(f.x), __float2half_rn(f.y),
                        __float2half_rn(f.z), __float2half_rn(f.w)};
        *(uint2*)&g_wh[off] = *(uint2*)hv;
    } else if (i < WO_END) {
        size_t off = (i - W_END) * 4;
        float4 f = *(const float4*)(wo + off);
        __half hv[4] = {__float2half_rn(f.x), __float2half_rn(f.y),
                        __float2half_rn(f.z), __float2half_rn(f.w)};
        *(uint2*)&g_woh[off] = *(uint2*)hv;
    } else if (i < FILL_END) {
        int idx = (int)(i - WO_END);         // B*H*64*DK items
        int d = idx & 63;
        int s = (idx >> 6) & 63;
        int h = (idx >> 12) & 15;
        int b = idx >> 16;
        size_t o = (((size_t)(b * HEADS + h)) * NKV_PAD + 1024 + s) * DK + d;
        if (s < MSLOT) {
            g_k[o] = __float2half_rn(32.0f * m_k[s * DMODEL + h * 64 + d]);
            g_v[o] = __float2half_rn(2.8284271247461903f * m_v[s * DMODEL + h * 64 + d]);
        } else {
            g_k[o] = __float2half_rn(0.0f);
            g_v[o] = __float2half_rn(0.0f);
        }
    }
}

// ------------------------- HMMA GEMM (128x128, BK=64, 3-stage ring) ---------
static constexpr int TILE_BYTES = 128 * 128;         // 16KB per operand tile
static constexpr int STAGE_B = 2 * TILE_BYTES;       // 32KB
static constexpr int GEMM_SMEM = 3 * STAGE_B;        // 98304

template <int NT, int EPI>
__global__ void __launch_bounds__(256, 2) gemm_mma(const float* __restrict__ bias,
                                                   float* __restrict__ outp) {
    extern __shared__ __align__(128) char sm[];
    const uint32_t smb = s2u(sm);
    const int tid = threadIdx.x, warp = tid >> 5, lane = tid & 31;

    const int lin = blockIdx.y * gridDim.x + blockIdx.x;
    const int bandsz = gridDim.x * 8;
    const int band = lin / bandsz, rem = lin % bandsz;
    const int by = band * 8 + (rem & 7);
    const int bx = rem >> 3;
    const int rowbase = by * 128, colbase = bx * 128;
    const int wr = (warp >> 2) * 64, wc = (warp & 3) * 32;

    const __half *ah, *bhp;
    if (EPI == 0) {
        const int z = colbase >> 10;
        ah = g_inh + (size_t)z * 8388608;
        bhp = g_wh;
    } else {
        ah = g_aoh;
        bhp = g_woh;
    }

    float acc[4][4][4];
#pragma unroll
    for (int i = 0; i < 4; i++)
#pragma unroll
        for (int j = 0; j < 4; j++)
#pragma unroll
            for (int u = 0; u < 4; u++) acc[i][j][u] = 0.0f;

    auto issue = [&](int kt) {
        const int slot = kt % 3;
        const int k0 = kt << 6;
        const __half* Ag = ah + (size_t)rowbase * 1024 + k0;
        const __half* Bg = bhp + (size_t)colbase * 1024 + k0;
        const uint32_t dstS = smb + slot * STAGE_B;
#pragma unroll
        for (int c8 = 0; c8 < 8; c8++) {
            int idx = tid + c8 * 256;            // 2048 x 16B chunks
            int isB = idx >> 10;
            int e = idx & 1023;
            int r = e >> 3, c = e & 7;
            const __half* src = (isB ? Bg : Ag) + (size_t)r * 1024 + c * 8;
            uint32_t dst = dstS + isB * TILE_BYTES + r * 128 + ((c ^ (r & 7)) * 16);
            cpasync16(dst, src);
        }
    };

    issue(0);
    asm volatile("cp.async.commit_group;" ::: "memory");
    issue(1);
    asm volatile("cp.async.commit_group;" ::: "memory");

    for (int kt = 0; kt < NT; kt++) {
        asm volatile("cp.async.wait_group 1;" ::: "memory");
        __syncthreads();

        const uint32_t aBase = smb + (kt % 3) * STAGE_B;
        const uint32_t bBase = aBase + TILE_BYTES;
#pragma unroll
        for (int k16 = 0; k16 < 4; k16++) {
            uint32_t a[4][4];
#pragma unroll
            for (int mt = 0; mt < 4; mt++) {
                int r = wr + mt * 16 + (lane & 15);
                int cc = k16 * 2 + (lane >> 4);
                LDM_X4(a[mt], aBase + r * 128 + ((cc ^ (r & 7)) * 16));
            }
            uint32_t b[2][4];
#pragma unroll
            for (int bt = 0; bt < 2; bt++) {
                int r = wc + bt * 16 + (lane & 7) + ((lane >> 4) & 1) * 8;
                int cc = k16 * 2 + ((lane >> 3) & 1);
                LDM_X4(b[bt], bBase + r * 128 + ((cc ^ (r & 7)) * 16));
            }
#pragma unroll
            for (int mt = 0; mt < 4; mt++)
#pragma unroll
                for (int nt = 0; nt < 4; nt++)
                    mma16816(acc[mt][nt], a[mt], b[nt >> 1][(nt & 1) * 2],
                             b[nt >> 1][(nt & 1) * 2 + 1]);
        }

        // issue kt+2 into slot (kt+2)%3 = slot of kt-1; all warps passed this
        // iteration's top sync, so iter kt-1 readers are done.
        if (kt + 2 < NT) issue(kt + 2);
        asm volatile("cp.async.commit_group;" ::: "memory");
    }

    const int r0 = lane >> 2, cp = (lane & 3) * 2;
#pragma unroll
    for (int mt = 0; mt < 4; mt++) {
#pragma unroll
        for (int nt = 0; nt < 4; nt++) {
            const float* cc = acc[mt][nt];
            int gr = rowbase + wr + mt * 16 + r0;
            int gc = colbase + wc + nt * 8 + cp;
            if (EPI == 0) {
                const int z = gc >> 10;
                __half* dst = (z == 0) ? g_q : (z == 1) ? g_k : g_v;
                const int L = (z == 0) ? NQ : NKV_PAD;
                float b0 = __half2float(__float2half_rn(bias[gc]));
                float b1 = __half2float(__float2half_rn(bias[gc + 1]));
                int cz = gc & 1023;
                int hh = cz >> 6, dk = cz & 63;
#pragma unroll
                for (int rh = 0; rh < 2; rh++) {
                    int g = gr + rh * 8;
                    int n = g >> 3, bb = g & 7;
                    size_t o = (((size_t)(bb * HEADS + hh)) * L + n) * 64 + dk;
                    __half hv[2] = {__float2half_rn(cc[rh * 2] + b0),
                                    __float2half_rn(cc[rh * 2 + 1] + b1)};
                    *(uint32_t*)&dst[o] = *(uint32_t*)hv;
                }
            } else {
                float b0 = bias[gc], b1 = bias[gc + 1];
#pragma unroll
                for (int rh = 0; rh < 2; rh++) {
                    int g = gr + rh * 8;
                    float2 v = make_float2(cc[rh * 2] + b0, cc[rh * 2 + 1] + b1);
                    *(float2*)&outp[(size_t)g * 1024 + gc] = v;
                }
            }
        }
    }
}

// ------------------------- flash attention (R8 config, proven 178us) --------
static constexpr int ATTN_SMEM = 16384 + 3 * 16384;   // Q + 3 KV stages

__global__ void __launch_bounds__(256, 2) attn_kernel(const float* __restrict__ mask) {
    extern __shared__ __align__(128) char smc[];
    const uint32_t smb = s2u(smc);
    const int tid = threadIdx.x, warp = tid >> 5, lane = tid & 31;
    const int qt = blockIdx.x, bh = blockIdx.y;
    const int q0 = qt * 128;
    const __half* qg = g_q + ((size_t)bh * NQ + q0) * DK;
    const __half* kg = g_k + (size_t)bh * NKV_PAD * DK;
    const __half* vg = g_v + (size_t)bh * NKV_PAD * DK;

    auto issueKV = [&](int t) {
        const uint32_t base = smb + 16384 + (t % 3) * 16384;
        const __half* kp = kg + (size_t)t * 64 * 64;
        const __half* vp = vg + (size_t)t * 64 * 64;
#pragma unroll
        for (int it = 0; it < 2; it++) {
            int idx = tid + it * 256;
            int r = idx >> 3, c = idx & 7;
            uint32_t so = r * 128 + ((c ^ (r & 7)) * 16);
            cpasync16(base + so, kp + (size_t)r * 64 + c * 8);
            cpasync16(base + 8192 + so, vp + (size_t)r * 64 + c * 8);
        }
    };

    issueKV(0);
    asm volatile("cp.async.commit_group;" ::: "memory");
    issueKV(1);
    asm volatile("cp.async.commit_group;" ::: "memory");

#pragma unroll
    for (int it = 0; it < 4; it++) {
        int idx = tid + it * 256;
        int r = idx >> 3, c = idx & 7;
        *(uint4*)(smc + r * 128 + ((c ^ (r & 7)) * 16)) =
            *(const uint4*)(qg + (size_t)r * 64 + c * 8);
    }
    __syncthreads();

    uint32_t qa[4][4];
    {
        const __half2 sc8 = __floats2half2_rn(0.125f, 0.125f);
        int r = warp * 16 + (lane & 7) + ((lane >> 3) & 1) * 8;
#pragma unroll
        for (int u = 0; u < 4; u++) {
            int c = u * 2 + (lane >> 4);
            LDM_X4(qa[u], smb + r * 128 + ((c ^ (r & 7)) * 16));
#pragma unroll
            for (int j = 0; j < 4; j++) {
                __half2 h = __hmul2(*(__half2*)&qa[u][j], sc8);
                qa[u][j] = *(uint32_t*)&h;
            }
        }
    }

    float o[8][4];
#pragma unroll
    for (int n = 0; n < 8; n++)
#pragma unroll
        for (int j = 0; j < 4; j++) o[n][j] = 0.0f;
    float mprevA = -1e30f, mprevB = -1e30f, laccA = 0.0f, laccB = 0.0f;

    const int rA = lane >> 2;
    const float* mrowA = mask + ((size_t)bh * NQ + q0 + warp * 16 + rA) * NQ +
                         2 * (lane & 3);
    const float* mrowB = mrowA + 8 * NQ;

    for (int t = 0; t < 17; t++) {
        asm volatile("cp.async.wait_group 1;" ::: "memory");
        __syncthreads();

        const uint32_t kb = smb + 16384 + (t % 3) * 16384;
        const uint32_t vb = kb + 8192;

        float s[8][4];
        if (t < 16) {
            const float* mA = mrowA + t * 64;
            const float* mB = mrowB + t * 64;
#pragma unroll
            for (int n = 0; n < 8; n++) {
                float2 xa = *(const float2*)(mA + n * 8);
                float2 xb = *(const float2*)(mB + n * 8);
                s[n][0] = xa.x; s[n][1] = xa.y;
                s[n][2] = xb.x; s[n][3] = xb.y;
            }
        } else {
            s[0][0] = s[0][1] = s[0][2] = s[0][3] = 0.0f;
#pragma unroll
            for (int n = 1; n < 8; n++)
                s[n][0] = s[n][1] = s[n][2] = s[n][3] = -1e30f;
        }

        {
            const int rn = (lane & 7) + ((lane >> 4) & 1) * 8;
            const int ck = (lane >> 3) & 1;
#pragma unroll
            for (int g = 0; g < 4; g++) {
                int r = g * 16 + rn;
#pragma unroll
                for (int u = 0; u < 4; u++) {
                    int c = u * 2 + ck;
                    uint32_t kb4[4];
                    LDM_X4(kb4, kb + r * 128 + ((c ^ (r & 7)) * 16));
                    mma16816(s[2 * g],     qa[u], kb4[0], kb4[1]);
                    mma16816(s[2 * g + 1], qa[u], kb4[2], kb4[3]);
                }
            }
        }

        float mxA = -1e30f, mxB = -1e30f;
#pragma unroll
        for (int n = 0; n < 8; n++) {
            mxA = fmaxf(mxA, fmaxf(s[n][0], s[n][1]));
            mxB = fmaxf(mxB, fmaxf(s[n][2], s[n][3]));
        }
        mxA = fmaxf(mxA, __shfl_xor_sync(0xffffffffu, mxA, 1));
        mxA = fmaxf(mxA, __shfl_xor_sync(0xffffffffu, mxA, 2));
        mxB = fmaxf(mxB, __shfl_xor_sync(0xffffffffu, mxB, 1));
        mxB = fmaxf(mxB, __shfl_xor_sync(0xffffffffu, mxB, 2));
        float mnA = fmaxf(mprevA, mxA), mnB = fmaxf(mprevB, mxB);
        float aA = __expf(mprevA - mnA), aB = __expf(mprevB - mnB);
        mprevA = mnA; mprevB = mnB;

        uint32_t pf[4][4];
        float sumA = 0.0f, sumB = 0.0f;
#pragma unroll
        for (int n = 0; n < 8; n++) {
            float p0 = __expf(s[n][0] - mnA);
            float p1 = __expf(s[n][1] - mnA);
            float p2 = __expf(s[n][2] - mnB);
            float p3 = __expf(s[n][3] - mnB);
            sumA += p0 + p1; sumB += p2 + p3;
            pf[n >> 1][(n & 1) * 2]     = packh2(p0, p1);
            pf[n >> 1][(n & 1) * 2 + 1] = packh2(p2, p3);
        }
        sumA += __shfl_xor_sync(0xffffffffu, sumA, 1);
        sumA += __shfl_xor_sync(0xffffffffu, sumA, 2);
        sumB += __shfl_xor_sync(0xffffffffu, sumB, 1);
        sumB += __shfl_xor_sync(0xffffffffu, sumB, 2);
        laccA = laccA * aA + sumA;
        laccB = laccB * aB + sumB;
#pragma unroll
        for (int n = 0; n < 8; n++) {
            o[n][0] *= aA; o[n][1] *= aA;
            o[n][2] *= aB; o[n][3] *= aB;
        }

        {
            int rr = (lane & 7) + ((lane >> 3) & 1) * 8;
#pragma unroll
            for (int u = 0; u < 4; u++) {
                int r = u * 16 + rr;
#pragma unroll
                for (int dp = 0; dp < 4; dp++) {
                    int c = dp * 2 + (lane >> 4);
                    uint32_t vb4[4];
                    LDM_X4_T(vb4, vb + r * 128 + ((c ^ (r & 7)) * 16));
                    mma16816(o[2 * dp],     pf[u], vb4[0], vb4[1]);
                    mma16816(o[2 * dp + 1], pf[u], vb4[2], vb4[3]);
                }
            }
        }

        if (t + 2 < 17) issueKV(t + 2);
        asm volatile("cp.async.commit_group;" ::: "memory");
    }

    const int b = bh >> 4, h = bh & 15;
    const int qrA = q0 + warp * 16 + rA;
    const float invA = 1.0f / laccA, invB = 1.0f / laccB;
#pragma unroll
    for (int n = 0; n < 8; n++) {
        int dk = h * 64 + n * 8 + 2 * (lane & 3);
        {
            __half hv[2] = {__float2half_rn(o[n][0] * invA),
                            __float2half_rn(o[n][1] * invA)};
            *(uint32_t*)&g_aoh[((size_t)qrA * BATCH + b) * DMODEL + dk] =
                *(uint32_t*)hv;
        }
        {
            __half hv[2] = {__float2half_rn(o[n][2] * invB),
                            __float2half_rn(o[n][3] * invB)};
            *(uint32_t*)&g_aoh[((size_t)(qrA + 8) * BATCH + b) * DMODEL + dk] =
                *(uint32_t*)hv;
        }
    }
}

// ------------------------- launch -------------------------------------------
extern "C" void kernel_launch(void* const* d_in, const int* in_sizes, int n_in,
                              void* d_out, int out_size) {
    const float* queries = (const float*)d_in[0];
    const float* keys    = (const float*)d_in[1];
    const float* values  = (const float*)d_in[2];
    const float* m_k     = (const float*)d_in[3];
    const float* m_v     = (const float*)d_in[4];
    const float* mask    = (const float*)d_in[5];
    const float* in_w    = (const float*)d_in[6];
    const float* in_b    = (const float*)d_in[7];
    const float* out_w   = (const float*)d_in[8];
    const float* out_b   = (const float*)d_in[9];
    float* out = (float*)d_out;
    (void)in_sizes; (void)n_in; (void)out_size;

    cudaFuncSetAttribute(attn_kernel, cudaFuncAttributeMaxDynamicSharedMemorySize,
                         ATTN_SMEM);
    cudaFuncSetAttribute(gemm_mma<16, 0>, cudaFuncAttributeMaxDynamicSharedMemorySize,
                         GEMM_SMEM);
    cudaFuncSetAttribute(gemm_mma<16, 1>, cudaFuncAttributeMaxDynamicSharedMemorySize,
                         GEMM_SMEM);

    convert_kernel<<<30720, 256>>>(queries, keys, values, in_w, out_w, m_k, m_v);
    gemm_mma<16, 0><<<dim3(24, 64), 256, GEMM_SMEM>>>(in_b, nullptr);  // QKV proj
    attn_kernel<<<dim3(8, 128), 256, ATTN_SMEM>>>(mask);
    gemm_mma<16, 1><<<dim3(8, 64), 256, GEMM_SMEM>>>(out_b, out);      // out proj
}